// round 15
// baseline (speedup 1.0000x reference)
#include <cuda_runtime.h>
#include <cuda_bf16.h>
#include <cstdint>

#define D_MODEL 1024
#define D_FF    4096
#define BATCH   4
#define SEQ     2048
#define MROWS   (BATCH * SEQ)   // 8192
#define MAXF    8192
#define FLAG_THRESH 0.45f
#define WARMUP  264             // exact-path warmup: 0.9^264 ~ 6e-13

// ---------------- scratch (static __device__, no allocations) ----------------
__device__ __nv_bfloat16 g_X[(size_t)MROWS * D_MODEL];  // xema bf16 (16.8 MB)
__device__ __nv_bfloat16 g_W1[(size_t)D_FF * D_MODEL];  // W1 bf16   ( 8.4 MB)
__device__ int      g_nflag;
__device__ uint32_t g_flags[MAXF];                      // packed m*4096+f

// ===== fused prep: blocks [0,4096) convert W1; blocks [4096,4224) run EMA ====
// EMA: chunk=256 steps + 128-step warm-up (0.9^128 = 1.4e-6 << 0.03 margin).
#define CVT_BLOCKS 4096
#define EMA_BLOCKS 128
#define CH 256
__global__ void prep_kernel(const float* __restrict__ W1src,
                            const float* __restrict__ spikes) {
    int blk = blockIdx.x;
    if (blk < CVT_BLOCKS) {
        int i = blk * 256 + threadIdx.x;        // over float4 of W1 (1M)
        if (i == 0) g_nflag = 0;
        float4 v = reinterpret_cast<const float4*>(W1src)[i];
        reinterpret_cast<__nv_bfloat162*>(g_W1)[i * 2 + 0] = __floats2bfloat162_rn(v.x, v.y);
        reinterpret_cast<__nv_bfloat162*>(g_W1)[i * 2 + 1] = __floats2bfloat162_rn(v.z, v.w);
    } else {
        int idx = (blk - CVT_BLOCKS) * 256 + threadIdx.x;  // 0..32767
        int d = idx & (D_MODEL - 1);
        int c = (idx >> 10) & 7;                           // chunk id (T/CH = 8)
        int b = idx >> 13;
        const float* x = spikes + (size_t)b * SEQ * D_MODEL + d;
        int t0 = c * CH;
        int start = t0 - 128; if (start < 0) start = 0;

        float act = 0.f;
        #pragma unroll 8
        for (int t = start; t < t0; t++)
            act = fmaf(0.9f, act, 0.1f * x[(size_t)t * D_MODEL]);

        __nv_bfloat16* o = g_X + ((size_t)b * SEQ + t0) * D_MODEL + d;
        #pragma unroll 8
        for (int t = 0; t < CH; t++) {
            act = fmaf(0.9f, act, 0.1f * x[(size_t)(t0 + t) * D_MODEL]);
            o[(size_t)t * D_MODEL] = __float2bfloat16(act);
        }
    }
}

// ===== bf16 GEMM screen + fused output zeroing =====
// acc[M,F] = X[M,D] @ W1[F,D]^T ; flag acc > 0.45.
// BM=256, BN=128, BK=32, 512 threads (16 warps, each 64x32), 4-stage cp.async.
#define BM 256
#define BN 128
#define BK 32
#define KTILES (D_MODEL / BK)        // 32
#define SROWB 80                     // padded row: 40 bf16 = 80B
#define STAGE_A (BM * SROWB)         // 20480
#define STAGE_B (BN * SROWB)         // 10240
#define STAGE_BYTES (STAGE_A + STAGE_B)
#define GEMM_SMEM (4 * STAGE_BYTES)  // 122880
#define GEMM_THREADS_TOTAL ((D_FF / BN) * (MROWS / BM) * 512)   // 524288

__device__ __forceinline__ void cp_async16(uint32_t dst, const void* src) {
    asm volatile("cp.async.cg.shared.global [%0], [%1], 16;\n" :: "r"(dst), "l"(src));
}

__global__ void __launch_bounds__(512, 1) gemm_kernel(float4* __restrict__ out4,
                                                      int n4) {
    extern __shared__ char dyn_smem[];
    const uint32_t smem0 = (uint32_t)__cvta_generic_to_shared(dyn_smem);

    const int tid  = threadIdx.x;
    const int bm   = blockIdx.y * BM;   // 32 tiles
    const int bn   = blockIdx.x * BN;   // 32 tiles
    const int warp = tid >> 5;
    const int lane = tid & 31;
    const int warp_m = (warp & 3) * 64;
    const int warp_n = (warp >> 2) * 32;
    const int grp = lane >> 2;
    const int q   = lane & 3;

    const __nv_bfloat16* gA = g_X  + (size_t)bm * D_MODEL;
    const __nv_bfloat16* gB = g_W1 + (size_t)bn * D_MODEL;

    float acc[4][4][4];
    #pragma unroll
    for (int i = 0; i < 4; i++)
        #pragma unroll
        for (int j = 0; j < 4; j++)
            #pragma unroll
            for (int k = 0; k < 4; k++) acc[i][j][k] = 0.f;

    auto load_stage = [&](int kt) {
        const int s = kt & 3;
        const int k0 = kt * BK;
        const uint32_t baseA = smem0 + s * STAGE_BYTES;
        const uint32_t baseB = baseA + STAGE_A;
        #pragma unroll
        for (int i = 0; i < 2; i++) {
            int c = tid + i * 512;
            int row = c >> 2, kk = (c & 3) * 8;
            cp_async16(baseA + row * SROWB + kk * 2,
                       gA + (size_t)row * D_MODEL + k0 + kk);
        }
        {
            int c = tid;
            int row = c >> 2, kk = (c & 3) * 8;
            cp_async16(baseB + row * SROWB + kk * 2,
                       gB + (size_t)row * D_MODEL + k0 + kk);
        }
    };

    #pragma unroll
    for (int p = 0; p < 3; p++) {
        load_stage(p);
        asm volatile("cp.async.commit_group;\n" ::: "memory");
    }

    // fused zero of the output buffer, overlapped with pipeline fill
    {
        int gtid = (blockIdx.y * gridDim.x + blockIdx.x) * 512 + tid;
        float4 z = make_float4(0.f, 0.f, 0.f, 0.f);
        #pragma unroll
        for (int k = 0; k < 16; k++) {
            int i = gtid + k * GEMM_THREADS_TOTAL;
            if (i < n4) out4[i] = z;
        }
    }

    for (int kt = 0; kt < KTILES; kt++) {
        const int s = kt & 3;
        asm volatile("cp.async.wait_group 2;\n" ::: "memory");
        __syncthreads();

        // issue next-stage loads FIRST so they overlap with this tile's math
        const int fill = kt + 3;
        if (fill < KTILES) load_stage(fill);
        asm volatile("cp.async.commit_group;\n" ::: "memory");

        const uint32_t baseA = smem0 + s * STAGE_BYTES;
        const uint32_t baseB = baseA + STAGE_A;

        #pragma unroll
        for (int ks = 0; ks < 2; ks++) {
            const int kb = ks * 16;
            uint32_t a[4][4];
            #pragma unroll
            for (int fm = 0; fm < 4; fm++) {
                int row = warp_m + fm * 16 + (lane & 15);
                int col = kb + ((lane >> 4) << 3);
                uint32_t addr = baseA + row * SROWB + col * 2;
                asm volatile(
                    "ldmatrix.sync.aligned.m8n8.x4.shared.b16 {%0,%1,%2,%3}, [%4];\n"
                    : "=r"(a[fm][0]), "=r"(a[fm][1]), "=r"(a[fm][2]), "=r"(a[fm][3])
                    : "r"(addr));
            }
            uint32_t bf[2][4];
            #pragma unroll
            for (int fn2 = 0; fn2 < 2; fn2++) {
                int row = warp_n + fn2 * 16 + (lane & 7) + ((lane >> 4) << 3);
                int col = kb + (((lane >> 3) & 1) << 3);
                uint32_t addr = baseB + row * SROWB + col * 2;
                asm volatile(
                    "ldmatrix.sync.aligned.m8n8.x4.shared.b16 {%0,%1,%2,%3}, [%4];\n"
                    : "=r"(bf[fn2][0]), "=r"(bf[fn2][1]), "=r"(bf[fn2][2]), "=r"(bf[fn2][3])
                    : "r"(addr));
            }
            #pragma unroll
            for (int fm = 0; fm < 4; fm++) {
                #pragma unroll
                for (int fn = 0; fn < 4; fn++) {
                    uint32_t b0 = bf[fn >> 1][(fn & 1) * 2 + 0];
                    uint32_t b1 = bf[fn >> 1][(fn & 1) * 2 + 1];
                    asm volatile(
                        "mma.sync.aligned.m16n8k16.row.col.f32.bf16.bf16.f32 "
                        "{%0,%1,%2,%3}, {%4,%5,%6,%7}, {%8,%9}, {%0,%1,%2,%3};\n"
                        : "+f"(acc[fm][fn][0]), "+f"(acc[fm][fn][1]),
                          "+f"(acc[fm][fn][2]), "+f"(acc[fm][fn][3])
                        : "r"(a[fm][0]), "r"(a[fm][1]), "r"(a[fm][2]), "r"(a[fm][3]),
                          "r"(b0), "r"(b1));
                }
            }
        }
    }

    // epilogue: flag any mixed > FLAG_THRESH
    #pragma unroll
    for (int fm = 0; fm < 4; fm++) {
        #pragma unroll
        for (int fn = 0; fn < 4; fn++) {
            #pragma unroll
            for (int e = 0; e < 4; e++) {
                if (acc[fm][fn][e] > FLAG_THRESH) {
                    int m = bm + warp_m + fm * 16 + grp + ((e >> 1) ? 8 : 0);
                    int f = bn + warp_n + fn * 8 + q * 2 + (e & 1);
                    int idx = atomicAdd(&g_nflag, 1);
                    if (idx < MAXF) g_flags[idx] = (uint32_t)(m * D_FF + f);
                }
            }
        }
    }
}

// ------- exact path: fp32 recompute with 264-step warmup (expected 0 flags) --
__global__ void exact_kernel(const float* __restrict__ spikes,
                             const float* __restrict__ W1,
                             const float* __restrict__ Wr,
                             const float* __restrict__ W2,
                             float* __restrict__ out) {
    int n = g_nflag; if (n > MAXF) n = MAXF;
    if (n == 0) return;
    int warp = threadIdx.x >> 5, lane = threadIdx.x & 31;
    for (int e = blockIdx.x * (blockDim.x >> 5) + warp; e < n;
         e += gridDim.x * (blockDim.x >> 5)) {
        uint32_t p = g_flags[e];
        int f = (int)(p & (D_FF - 1));
        int m = (int)(p / D_FF);
        int b = m >> 11, t1 = m & (SEQ - 1);
        int ws = t1 - WARMUP; if (ws < 0) ws = 0;

        const float* X  = spikes + (size_t)b * SEQ * D_MODEL;
        const float* w1 = W1 + (size_t)f * D_MODEL;

        float em[32];
        #pragma unroll
        for (int j = 0; j < 32; j++) em[j] = 0.f;
        for (int t = ws; t <= t1; t++) {
            const float* x = X + (size_t)t * D_MODEL + lane;
            #pragma unroll
            for (int j = 0; j < 32; j++)
                em[j] = fmaf(0.9f, em[j], 0.1f * x[j * 32]);
        }
        float part = 0.f;
        #pragma unroll
        for (int j = 0; j < 32; j++)
            part = fmaf(em[j], w1[lane + j * 32], part);
        #pragma unroll
        for (int o = 16; o; o >>= 1) part += __shfl_xor_sync(~0u, part, o);

        if (part > 0.5f) {
            const float* wr = Wr + (size_t)f * D_MODEL;
            const float* xt = X + (size_t)t1 * D_MODEL;
            float sr = 0.f;
            for (int d = lane; d < D_MODEL; d += 32)
                sr = fmaf(xt[d], wr[d], sr);
            #pragma unroll
            for (int o = 16; o; o >>= 1) sr += __shfl_xor_sync(~0u, sr, o);
            float r = 1.f / (1.f + expf(-sr));
            float* o_ = out + ((size_t)b * SEQ + t1) * D_MODEL;
            for (int d = lane; d < D_MODEL; d += 32)
                atomicAdd(&o_[d], r * W2[(size_t)d * D_FF + f]);
        }
    }
}

// ---------------- entry ----------------
extern "C" void kernel_launch(void* const* d_in, const int* in_sizes, int n_in,
                              void* d_out, int out_size) {
    const float* spikes = (const float*)d_in[0];   // [B,T,D]
    const float* W1     = (const float*)d_in[1];   // [F,D]
    const float* W2     = (const float*)d_in[2];   // [D,F]
    const float* Wr     = (const float*)d_in[3];   // [F,D]
    float* out = (float*)d_out;
    (void)in_sizes; (void)n_in;

    prep_kernel<<<CVT_BLOCKS + EMA_BLOCKS, 256>>>(W1, spikes);

    cudaFuncSetAttribute(gemm_kernel, cudaFuncAttributeMaxDynamicSharedMemorySize, GEMM_SMEM);
    dim3 grid(D_FF / BN, MROWS / BM);   // (32, 32)
    gemm_kernel<<<grid, 512, GEMM_SMEM>>>((float4*)out, out_size / 4);

    exact_kernel<<<64, 256>>>(spikes, W1, Wr, W2, out);
}

// round 16
// speedup vs baseline: 1.0705x; 1.0705x over previous
#include <cuda_runtime.h>
#include <cuda_bf16.h>
#include <cstdint>

#define D_MODEL 1024
#define D_FF    4096
#define BATCH   4
#define SEQ     2048
#define MROWS   (BATCH * SEQ)   // 8192
#define MAXF    8192
#define FLAG_THRESH 0.45f
#define WARMUP  264             // exact-path warmup: 0.9^264 ~ 6e-13

// ---------------- scratch (static __device__, no allocations) ----------------
__device__ __nv_bfloat16 g_X[(size_t)MROWS * D_MODEL];  // xema bf16 (16.8 MB)
__device__ __nv_bfloat16 g_W1[(size_t)D_FF * D_MODEL];  // W1 bf16   ( 8.4 MB)
__device__ int      g_nflag;
__device__ uint32_t g_flags[MAXF];                      // packed m*4096+f

// ---------------- fp32 -> bf16 convert for W1 (+ flag reset) -----------------
__global__ void cvtW1_kernel(const float* __restrict__ src) {
    int i = blockIdx.x * blockDim.x + threadIdx.x;
    if (i == 0) g_nflag = 0;
    float4 v = reinterpret_cast<const float4*>(src)[i];
    reinterpret_cast<__nv_bfloat162*>(g_W1)[i * 2 + 0] = __floats2bfloat162_rn(v.x, v.y);
    reinterpret_cast<__nv_bfloat162*>(g_W1)[i * 2 + 1] = __floats2bfloat162_rn(v.z, v.w);
}

// ---------------- EMA over time (chunk=128 + 128-step warm-up) ---------------
#define CH 128
__global__ void ema_kernel(const float* __restrict__ spikes) {
    int idx = blockIdx.x * blockDim.x + threadIdx.x;   // 65536 threads
    int d = idx & (D_MODEL - 1);
    int c = (idx >> 10) & 15;                          // chunk id (T/CH = 16)
    int b = idx >> 14;
    const float* x = spikes + (size_t)b * SEQ * D_MODEL + d;
    int t0 = c * CH;
    int start = t0 - CH; if (start < 0) start = 0;

    float act = 0.f;
    #pragma unroll 8
    for (int t = start; t < t0; t++)
        act = fmaf(0.9f, act, 0.1f * x[(size_t)t * D_MODEL]);

    __nv_bfloat16* o = g_X + ((size_t)b * SEQ + t0) * D_MODEL + d;
    #pragma unroll 8
    for (int t = 0; t < CH; t++) {
        act = fmaf(0.9f, act, 0.1f * x[(size_t)(t0 + t) * D_MODEL]);
        o[(size_t)t * D_MODEL] = __float2bfloat16(act);
    }
}

// ===== bf16 GEMM screen + fused output zeroing; 2 CTAs/SM =====
// BM=128, BN=128, BK=32, 256 threads (8 warps, each 64x32), 4-stage cp.async.
// 80KB smem/CTA -> 2 co-resident CTAs/SM = two independent barrier groups.
#define BM 128
#define BN 128
#define BK 32
#define KTILES (D_MODEL / BK)        // 32
#define SROWB 80                     // padded row: 40 bf16 = 80B
#define STAGE_A (BM * SROWB)         // 10240
#define STAGE_B (BN * SROWB)         // 10240
#define STAGE_BYTES (STAGE_A + STAGE_B)
#define GEMM_SMEM (4 * STAGE_BYTES)  // 81920
#define GEMM_CTAS ((D_FF / BN) * (MROWS / BM))       // 32*64 = 2048
#define GEMM_THREADS_TOTAL (GEMM_CTAS * 256)         // 524288

__device__ __forceinline__ void cp_async16(uint32_t dst, const void* src) {
    asm volatile("cp.async.cg.shared.global [%0], [%1], 16;\n" :: "r"(dst), "l"(src));
}

__global__ void __launch_bounds__(256, 2) gemm_kernel(float4* __restrict__ out4,
                                                      int n4) {
    extern __shared__ char dyn_smem[];
    const uint32_t smem0 = (uint32_t)__cvta_generic_to_shared(dyn_smem);

    const int tid  = threadIdx.x;
    const int bm   = blockIdx.y * BM;   // 64 tiles
    const int bn   = blockIdx.x * BN;   // 32 tiles
    const int warp = tid >> 5;
    const int lane = tid & 31;
    const int warp_m = (warp & 1) * 64;     // 2 m-groups
    const int warp_n = (warp >> 1) * 32;    // 4 n-groups
    const int grp = lane >> 2;
    const int q   = lane & 3;

    const __nv_bfloat16* gA = g_X  + (size_t)bm * D_MODEL;
    const __nv_bfloat16* gB = g_W1 + (size_t)bn * D_MODEL;

    float acc[4][4][4];
    #pragma unroll
    for (int i = 0; i < 4; i++)
        #pragma unroll
        for (int j = 0; j < 4; j++)
            #pragma unroll
            for (int k = 0; k < 4; k++) acc[i][j][k] = 0.f;

    // per stage: A 128 rows x 64B = 512 chunks; B 512 chunks; 256 thr -> 2+2
    auto load_stage = [&](int kt) {
        const int s = kt & 3;
        const int k0 = kt * BK;
        const uint32_t baseA = smem0 + s * STAGE_BYTES;
        const uint32_t baseB = baseA + STAGE_A;
        #pragma unroll
        for (int i = 0; i < 2; i++) {
            int c = tid + i * 256;
            int row = c >> 2, kk = (c & 3) * 8;
            cp_async16(baseA + row * SROWB + kk * 2,
                       gA + (size_t)row * D_MODEL + k0 + kk);
            cp_async16(baseB + row * SROWB + kk * 2,
                       gB + (size_t)row * D_MODEL + k0 + kk);
        }
    };

    #pragma unroll
    for (int p = 0; p < 3; p++) {
        load_stage(p);
        asm volatile("cp.async.commit_group;\n" ::: "memory");
    }

    // fused zero of the output buffer, overlapped with pipeline fill
    {
        int gtid = (blockIdx.y * gridDim.x + blockIdx.x) * 256 + tid;
        float4 z = make_float4(0.f, 0.f, 0.f, 0.f);
        #pragma unroll
        for (int k = 0; k < 16; k++) {
            int i = gtid + k * GEMM_THREADS_TOTAL;
            if (i < n4) out4[i] = z;
        }
    }

    for (int kt = 0; kt < KTILES; kt++) {
        const int s = kt & 3;
        asm volatile("cp.async.wait_group 2;\n" ::: "memory");
        __syncthreads();

        // issue next-stage loads first so they overlap this tile's math
        const int fill = kt + 3;
        if (fill < KTILES) load_stage(fill);
        asm volatile("cp.async.commit_group;\n" ::: "memory");

        const uint32_t baseA = smem0 + s * STAGE_BYTES;
        const uint32_t baseB = baseA + STAGE_A;

        #pragma unroll
        for (int ks = 0; ks < 2; ks++) {
            const int kb = ks * 16;
            uint32_t a[4][4];
            #pragma unroll
            for (int fm = 0; fm < 4; fm++) {
                int row = warp_m + fm * 16 + (lane & 15);
                int col = kb + ((lane >> 4) << 3);
                uint32_t addr = baseA + row * SROWB + col * 2;
                asm volatile(
                    "ldmatrix.sync.aligned.m8n8.x4.shared.b16 {%0,%1,%2,%3}, [%4];\n"
                    : "=r"(a[fm][0]), "=r"(a[fm][1]), "=r"(a[fm][2]), "=r"(a[fm][3])
                    : "r"(addr));
            }
            uint32_t bf[2][4];
            #pragma unroll
            for (int fn2 = 0; fn2 < 2; fn2++) {
                int row = warp_n + fn2 * 16 + (lane & 7) + ((lane >> 4) << 3);
                int col = kb + (((lane >> 3) & 1) << 3);
                uint32_t addr = baseB + row * SROWB + col * 2;
                asm volatile(
                    "ldmatrix.sync.aligned.m8n8.x4.shared.b16 {%0,%1,%2,%3}, [%4];\n"
                    : "=r"(bf[fn2][0]), "=r"(bf[fn2][1]), "=r"(bf[fn2][2]), "=r"(bf[fn2][3])
                    : "r"(addr));
            }
            #pragma unroll
            for (int fm = 0; fm < 4; fm++) {
                #pragma unroll
                for (int fn = 0; fn < 4; fn++) {
                    uint32_t b0 = bf[fn >> 1][(fn & 1) * 2 + 0];
                    uint32_t b1 = bf[fn >> 1][(fn & 1) * 2 + 1];
                    asm volatile(
                        "mma.sync.aligned.m16n8k16.row.col.f32.bf16.bf16.f32 "
                        "{%0,%1,%2,%3}, {%4,%5,%6,%7}, {%8,%9}, {%0,%1,%2,%3};\n"
                        : "+f"(acc[fm][fn][0]), "+f"(acc[fm][fn][1]),
                          "+f"(acc[fm][fn][2]), "+f"(acc[fm][fn][3])
                        : "r"(a[fm][0]), "r"(a[fm][1]), "r"(a[fm][2]), "r"(a[fm][3]),
                          "r"(b0), "r"(b1));
                }
            }
        }
    }

    // epilogue: flag any mixed > FLAG_THRESH
    #pragma unroll
    for (int fm = 0; fm < 4; fm++) {
        #pragma unroll
        for (int fn = 0; fn < 4; fn++) {
            #pragma unroll
            for (int e = 0; e < 4; e++) {
                if (acc[fm][fn][e] > FLAG_THRESH) {
                    int m = bm + warp_m + fm * 16 + grp + ((e >> 1) ? 8 : 0);
                    int f = bn + warp_n + fn * 8 + q * 2 + (e & 1);
                    int idx = atomicAdd(&g_nflag, 1);
                    if (idx < MAXF) g_flags[idx] = (uint32_t)(m * D_FF + f);
                }
            }
        }
    }
}

// ------- exact path: fp32 recompute with 264-step warmup (expected 0 flags) --
__global__ void exact_kernel(const float* __restrict__ spikes,
                             const float* __restrict__ W1,
                             const float* __restrict__ Wr,
                             const float* __restrict__ W2,
                             float* __restrict__ out) {
    int n = g_nflag; if (n > MAXF) n = MAXF;
    if (n == 0) return;
    int warp = threadIdx.x >> 5, lane = threadIdx.x & 31;
    for (int e = blockIdx.x * (blockDim.x >> 5) + warp; e < n;
         e += gridDim.x * (blockDim.x >> 5)) {
        uint32_t p = g_flags[e];
        int f = (int)(p & (D_FF - 1));
        int m = (int)(p / D_FF);
        int b = m >> 11, t1 = m & (SEQ - 1);
        int ws = t1 - WARMUP; if (ws < 0) ws = 0;

        const float* X  = spikes + (size_t)b * SEQ * D_MODEL;
        const float* w1 = W1 + (size_t)f * D_MODEL;

        float em[32];
        #pragma unroll
        for (int j = 0; j < 32; j++) em[j] = 0.f;
        for (int t = ws; t <= t1; t++) {
            const float* x = X + (size_t)t * D_MODEL + lane;
            #pragma unroll
            for (int j = 0; j < 32; j++)
                em[j] = fmaf(0.9f, em[j], 0.1f * x[j * 32]);
        }
        float part = 0.f;
        #pragma unroll
        for (int j = 0; j < 32; j++)
            part = fmaf(em[j], w1[lane + j * 32], part);
        #pragma unroll
        for (int o = 16; o; o >>= 1) part += __shfl_xor_sync(~0u, part, o);

        if (part > 0.5f) {
            const float* wr = Wr + (size_t)f * D_MODEL;
            const float* xt = X + (size_t)t1 * D_MODEL;
            float sr = 0.f;
            for (int d = lane; d < D_MODEL; d += 32)
                sr = fmaf(xt[d], wr[d], sr);
            #pragma unroll
            for (int o = 16; o; o >>= 1) sr += __shfl_xor_sync(~0u, sr, o);
            float r = 1.f / (1.f + expf(-sr));
            float* o_ = out + ((size_t)b * SEQ + t1) * D_MODEL;
            for (int d = lane; d < D_MODEL; d += 32)
                atomicAdd(&o_[d], r * W2[(size_t)d * D_FF + f]);
        }
    }
}

// ---------------- entry ----------------
extern "C" void kernel_launch(void* const* d_in, const int* in_sizes, int n_in,
                              void* d_out, int out_size) {
    const float* spikes = (const float*)d_in[0];   // [B,T,D]
    const float* W1     = (const float*)d_in[1];   // [F,D]
    const float* W2     = (const float*)d_in[2];   // [D,F]
    const float* Wr     = (const float*)d_in[3];   // [F,D]
    float* out = (float*)d_out;
    (void)in_sizes; (void)n_in;

    cvtW1_kernel<<<(D_FF * D_MODEL / 4) / 256, 256>>>(W1);       // + flag reset
    ema_kernel<<<(BATCH * 16 * D_MODEL) / 256, 256>>>(spikes);

    cudaFuncSetAttribute(gemm_kernel, cudaFuncAttributeMaxDynamicSharedMemorySize, GEMM_SMEM);
    dim3 grid(D_FF / BN, MROWS / BM);   // (32, 64)
    gemm_kernel<<<grid, 256, GEMM_SMEM>>>((float4*)out, out_size / 4);

    exact_kernel<<<64, 256>>>(spikes, W1, Wr, W2, out);
}